// round 15
// baseline (speedup 1.0000x reference)
#include <cuda_runtime.h>
#include <cuda_fp16.h>
#include <math.h>
#include <stdint.h>

// Model dims
#define NB   2
#define NT   2048
#define ND   768
#define NH   12
#define NHS  64
#define NL   6
#define NV   50257
#define NTOK (NB*NT)        // 4096
#define NQKV (3*ND)         // 2304
#define NFF  (4*ND)         // 3072

// ---------------- scratch (static device memory; no allocations) -----------
__device__ float  g_x[NTOK*ND];
__device__ __half g_h[NTOK*ND];
__device__ float  g_qkv[(size_t)NTOK*NQKV];
__device__ __half g_o[NTOK*ND];
__device__ __half g_mlp[(size_t)NTOK*NFF];
__device__ __half g_wqkvT[(size_t)NL*NQKV*ND];     // [l][n][k] fp16
__device__ __half g_woT [(size_t)NL*ND*ND];        // [l][n][k] fp16
__device__ __half g_w1T [(size_t)NL*NFF*ND];       // [l][n][k] fp16
__device__ __half g_w2T [(size_t)NL*ND*NFF];       // [l][n][k] fp16
__device__ __half g_headT[(size_t)NV*ND];          // [n][k]    fp16
__device__ float  g_loss;

// ---------------- small utility kernels ------------------------------------
__global__ void reset_loss_kernel() { g_loss = 0.0f; }

__global__ void repack_qkv_kernel(const float* __restrict__ wq,
                                  const float* __restrict__ wk,
                                  const float* __restrict__ wv) {
    int i = blockIdx.x * 256 + threadIdx.x;
    const int total = NL * NQKV * ND;
    if (i >= total) return;
    int d = i % ND;
    int c = (i / ND) % NQKV;
    int l = i / (ND * NQKV);
    int sec = c / ND;
    int c2  = c % ND;
    int h   = c2 / NHS;
    int e   = c2 % NHS;
    const float* w = (sec == 0) ? wq : (sec == 1) ? wk : wv;
    g_wqkvT[i] = __float2half(w[(((size_t)l * NH + h) * ND + d) * NHS + e]);
}

__global__ void transpose_kernel(const float* __restrict__ src,
                                 __half* __restrict__ dst, int R, int C) {
    __shared__ float t[32][33];
    size_t boff = (size_t)blockIdx.z * R * C;
    int c0 = blockIdx.x * 32, r0 = blockIdx.y * 32;
#pragma unroll
    for (int i = 0; i < 32; i += 8) {
        int x = c0 + threadIdx.x, y = r0 + threadIdx.y + i;
        if (x < C && y < R) t[threadIdx.y + i][threadIdx.x] = src[boff + (size_t)y * C + x];
    }
    __syncthreads();
#pragma unroll
    for (int i = 0; i < 32; i += 8) {
        int x = r0 + threadIdx.x, y = c0 + threadIdx.y + i;
        if (x < R && y < C)
            dst[boff + (size_t)y * R + x] = __float2half(t[threadIdx.x][threadIdx.y + i]);
    }
}

__global__ void embed_kernel(const int* __restrict__ idx,
                             const float* __restrict__ tok,
                             const float* __restrict__ pos) {
    int i = blockIdx.x * 256 + threadIdx.x;
    if (i >= NTOK * ND) return;
    int d = i % ND;
    int row = i / ND;
    int t = row % NT;
    int tokid = idx[row];
    g_x[i] = tok[(size_t)tokid * ND + d] + pos[t * ND + d];
}

// ---------------- layernorm (fp32 in, fp16 out) -----------------------------
__global__ __launch_bounds__(256)
void ln_kernel(const float* __restrict__ x, const float* __restrict__ s,
               const float* __restrict__ b, __half* __restrict__ out) {
    __shared__ float red[256];
    int row = blockIdx.x, tid = threadIdx.x;
    const float* xr = x + (size_t)row * ND;
    float v0 = xr[tid], v1 = xr[tid + 256], v2 = xr[tid + 512];
    red[tid] = v0 + v1 + v2;
    __syncthreads();
    for (int off = 128; off; off >>= 1) {
        if (tid < off) red[tid] += red[tid + off];
        __syncthreads();
    }
    float mean = red[0] * (1.0f / ND);
    __syncthreads();
    float d0 = v0 - mean, d1 = v1 - mean, d2 = v2 - mean;
    red[tid] = d0 * d0 + d1 * d1 + d2 * d2;
    __syncthreads();
    for (int off = 128; off; off >>= 1) {
        if (tid < off) red[tid] += red[tid + off];
        __syncthreads();
    }
    float rstd = rsqrtf(red[0] * (1.0f / ND) + 1e-5f);
    __half* orow = out + (size_t)row * ND;
    orow[tid]       = __float2half(d0 * rstd * s[tid]       + b[tid]);
    orow[tid + 256] = __float2half(d1 * rstd * s[tid + 256] + b[tid + 256]);
    orow[tid + 512] = __float2half(d2 * rstd * s[tid + 512] + b[tid + 512]);
}

// ---------------- FP16 tensor-core GEMM (R11 proven) ------------------------
// C[MxN] = A[MxK] @ Bt[NxK]^T  (+bias, +relu, +resid); A, Bt fp16 at rest.
// Block 128x128, BK=16, 256 threads = 8 warps (2x4), warp tile 64x32.

#define HSTR 24   // halves per smem row

__device__ __forceinline__ void store_out(float* p, float v)  { *p = v; }
__device__ __forceinline__ void store_out(__half* p, float v) { *p = __float2half(v); }

template <int EPI, typename CT>  // bit0: +bias[n], bit1: relu, bit2: +resid[m,n]
__global__ __launch_bounds__(256)
void hgemm(const __half* __restrict__ A, const __half* __restrict__ Bt,
           const float* __restrict__ bias, const float* __restrict__ resid,
           CT* __restrict__ C, int M, int N, int K) {
    __shared__ __align__(16) __half As[128 * HSTR];
    __shared__ __align__(16) __half Bs[128 * HSTR];
    const int tid  = threadIdx.x;
    const int lane = tid & 31;
    const int warp = tid >> 5;
    const int wm = (warp >> 2) * 64;
    const int wn = (warp & 3) * 32;
    const int row0 = blockIdx.x * 128, col0 = blockIdx.y * 128;

    float acc[4][4][4];
#pragma unroll
    for (int mf = 0; mf < 4; mf++)
#pragma unroll
        for (int nf = 0; nf < 4; nf++)
#pragma unroll
            for (int j = 0; j < 4; j++) acc[mf][nf][j] = 0.0f;

    const int r  = tid >> 1;
    const int hc = (tid & 1) * 8;
    const __half* Ap = A + (size_t)(row0 + r) * K + hc;
    const int  rb  = col0 + r;
    const bool bok = rb < N;
    const __half* Bp = Bt + (size_t)(bok ? rb : 0) * K + hc;

    uint4 pa, pb;
    const uint4 zero4 = make_uint4(0u, 0u, 0u, 0u);
    const int KT = K / 16;

    pa = *reinterpret_cast<const uint4*>(Ap);
    pb = bok ? *reinterpret_cast<const uint4*>(Bp) : zero4;

    for (int kt = 0; kt < KT; kt++) {
        *reinterpret_cast<uint4*>(&As[r * HSTR + hc]) = pa;
        *reinterpret_cast<uint4*>(&Bs[r * HSTR + hc]) = pb;
        __syncthreads();
        if (kt + 1 < KT) {
            int k0 = (kt + 1) * 16;
            pa = *reinterpret_cast<const uint4*>(Ap + k0);
            pb = bok ? *reinterpret_cast<const uint4*>(Bp + k0) : zero4;
        }

        const int g   = lane >> 2;
        const int kq2 = (lane & 3) * 2;
        unsigned af[4][4], bf[4][2];
#pragma unroll
        for (int mf = 0; mf < 4; mf++) {
            int m = wm + mf * 16 + g;
            af[mf][0] = *reinterpret_cast<const unsigned*>(&As[m * HSTR + kq2]);
            af[mf][1] = *reinterpret_cast<const unsigned*>(&As[(m + 8) * HSTR + kq2]);
            af[mf][2] = *reinterpret_cast<const unsigned*>(&As[m * HSTR + kq2 + 8]);
            af[mf][3] = *reinterpret_cast<const unsigned*>(&As[(m + 8) * HSTR + kq2 + 8]);
        }
#pragma unroll
        for (int nf = 0; nf < 4; nf++) {
            int n = wn + nf * 8 + g;
            bf[nf][0] = *reinterpret_cast<const unsigned*>(&Bs[n * HSTR + kq2]);
            bf[nf][1] = *reinterpret_cast<const unsigned*>(&Bs[n * HSTR + kq2 + 8]);
        }
#pragma unroll
        for (int mf = 0; mf < 4; mf++)
#pragma unroll
            for (int nf = 0; nf < 4; nf++)
                asm volatile(
                    "mma.sync.aligned.m16n8k16.row.col.f32.f16.f16.f32 "
                    "{%0,%1,%2,%3}, {%4,%5,%6,%7}, {%8,%9}, {%0,%1,%2,%3};"
                    : "+f"(acc[mf][nf][0]), "+f"(acc[mf][nf][1]),
                      "+f"(acc[mf][nf][2]), "+f"(acc[mf][nf][3])
                    : "r"(af[mf][0]), "r"(af[mf][1]), "r"(af[mf][2]), "r"(af[mf][3]),
                      "r"(bf[nf][0]), "r"(bf[nf][1]));
        __syncthreads();
    }

#pragma unroll
    for (int mf = 0; mf < 4; mf++) {
        int r0 = row0 + wm + mf * 16 + (lane >> 2);
#pragma unroll
        for (int nf = 0; nf < 4; nf++) {
            int n0 = col0 + wn + nf * 8 + 2 * (lane & 3);
#pragma unroll
            for (int half = 0; half < 2; half++) {
                int rr = r0 + half * 8;
#pragma unroll
                for (int j = 0; j < 2; j++) {
                    int n = n0 + j;
                    if (n < N) {
                        float v = acc[mf][nf][half * 2 + j];
                        if (EPI & 1) v += bias[n];
                        if (EPI & 2) v = fmaxf(v, 0.0f);
                        if (EPI & 4) v += resid[(size_t)rr * N + n];
                        store_out(&C[(size_t)rr * N + n], v);
                    }
                }
            }
        }
    }
}

// ---------------- BM=64 GEMM variant (for small-N GEMMs: full chip fill) ----
// Block 64x128, BK=16, 256 threads = 8 warps (2x4), warp tile 32x32.
// Used for wo / w2 (N=768): grid 64x6 = 384 CTAs vs 192 for BM=128.
template <int EPI, typename CT>
__global__ __launch_bounds__(256)
void hgemm64(const __half* __restrict__ A, const __half* __restrict__ Bt,
             const float* __restrict__ bias, const float* __restrict__ resid,
             CT* __restrict__ C, int M, int N, int K) {
    __shared__ __align__(16) __half As[64 * HSTR];
    __shared__ __align__(16) __half Bs[128 * HSTR];
    const int tid  = threadIdx.x;
    const int lane = tid & 31;
    const int warp = tid >> 5;
    const int wm = (warp >> 2) * 32;   // 0 or 32
    const int wn = (warp & 3) * 32;
    const int row0 = blockIdx.x * 64, col0 = blockIdx.y * 128;

    float acc[2][4][4];
#pragma unroll
    for (int mf = 0; mf < 2; mf++)
#pragma unroll
        for (int nf = 0; nf < 4; nf++)
#pragma unroll
            for (int j = 0; j < 4; j++) acc[mf][nf][j] = 0.0f;

    // B load: all 256 threads, row r = tid>>1 (0..127), chunk hc = (tid&1)*8
    // A load: threads < 128, row ra = tid>>1 (0..63)
    const int r  = tid >> 1;
    const int hc = (tid & 1) * 8;
    const bool aok = tid < 128;
    const __half* Ap = A + (size_t)(row0 + (aok ? r : 0)) * K + hc;
    const int  rb  = col0 + r;
    const bool bok = rb < N;
    const __half* Bp = Bt + (size_t)(bok ? rb : 0) * K + hc;

    uint4 pa, pb;
    const uint4 zero4 = make_uint4(0u, 0u, 0u, 0u);
    const int KT = K / 16;

    pa = aok ? *reinterpret_cast<const uint4*>(Ap) : zero4;
    pb = bok ? *reinterpret_cast<const uint4*>(Bp) : zero4;

    for (int kt = 0; kt < KT; kt++) {
        if (aok) *reinterpret_cast<uint4*>(&As[r * HSTR + hc]) = pa;
        *reinterpret_cast<uint4*>(&Bs[r * HSTR + hc]) = pb;
        __syncthreads();
        if (kt + 1 < KT) {
            int k0 = (kt + 1) * 16;
            pa = aok ? *reinterpret_cast<const uint4*>(Ap + k0) : zero4;
            pb = bok ? *reinterpret_cast<const uint4*>(Bp + k0) : zero4;
        }

        const int g   = lane >> 2;
        const int kq2 = (lane & 3) * 2;
        unsigned af[2][4], bf[4][2];
#pragma unroll
        for (int mf = 0; mf < 2; mf++) {
            int m = wm + mf * 16 + g;
            af[mf][0] = *reinterpret_cast<const unsigned*>(&As[m * HSTR + kq2]);
            af[mf][1] = *reinterpret_cast<const unsigned*>(&As[(m + 8) * HSTR + kq2]);
            af[mf][2] = *reinterpret_cast<const unsigned*>(&As[m * HSTR + kq2 + 8]);
            af[mf][3] = *reinterpret_cast<const unsigned*>(&As[(m + 8) * HSTR + kq2 + 8]);
        }
#pragma unroll
        for (int nf = 0; nf < 4; nf++) {
            int n = wn + nf * 8 + g;
            bf[nf][0] = *reinterpret_cast<const unsigned*>(&Bs[n * HSTR + kq2]);
            bf[nf][1] = *reinterpret_cast<const unsigned*>(&Bs[n * HSTR + kq2 + 8]);
        }
#pragma unroll
        for (int mf = 0; mf < 2; mf++)
#pragma unroll
            for (int nf = 0; nf < 4; nf++)
                asm volatile(
                    "mma.sync.aligned.m16n8k16.row.col.f32.f16.f16.f32 "
                    "{%0,%1,%2,%3}, {%4,%5,%6,%7}, {%8,%9}, {%0,%1,%2,%3};"
                    : "+f"(acc[mf][nf][0]), "+f"(acc[mf][nf][1]),
                      "+f"(acc[mf][nf][2]), "+f"(acc[mf][nf][3])
                    : "r"(af[mf][0]), "r"(af[mf][1]), "r"(af[mf][2]), "r"(af[mf][3]),
                      "r"(bf[nf][0]), "r"(bf[nf][1]));
        __syncthreads();
    }

#pragma unroll
    for (int mf = 0; mf < 2; mf++) {
        int r0 = row0 + wm + mf * 16 + (lane >> 2);
#pragma unroll
        for (int nf = 0; nf < 4; nf++) {
            int n0 = col0 + wn + nf * 8 + 2 * (lane & 3);
#pragma unroll
            for (int half = 0; half < 2; half++) {
                int rr = r0 + half * 8;
#pragma unroll
                for (int j = 0; j < 2; j++) {
                    int n = n0 + j;
                    if (n < N) {
                        float v = acc[mf][nf][half * 2 + j];
                        if (EPI & 1) v += bias[n];
                        if (EPI & 2) v = fmaxf(v, 0.0f);
                        if (EPI & 4) v += resid[(size_t)rr * N + n];
                        store_out(&C[(size_t)rr * N + n], v);
                    }
                }
            }
        }
    }
}

// ---------------- smem-tiled streaming causal attention (R11 proven) --------
#define SCH 32    // keys per smem chunk

__global__ __launch_bounds__(256)
void attn_kernel(const float* __restrict__ qkv, __half* __restrict__ o) {
    __shared__ float Ks[SCH * NHS];
    __shared__ float Vs[SCH * NHS];

    const int tid  = threadIdx.x;
    const int lane = tid & 31;
    const int wi   = tid >> 5;
    const int qblk = blockIdx.x % (NT / 32);
    const int bh   = blockIdx.x / (NT / 32);
    const int b    = bh / NH, h = bh % NH;
    const int t0c  = qblk * 32;
    const int t0   = t0c + wi * 4;

    const float* base = qkv + (size_t)b * NT * NQKV;
    const float* qb = base + h * NHS;
    const float* kb = base + ND + h * NHS;
    const float* vb = base + 2 * ND + h * NHS;

    float q0[4], q1[4];
#pragma unroll
    for (int i = 0; i < 4; i++) {
        q0[i] = qb[(size_t)(t0 + i) * NQKV + lane];
        q1[i] = qb[(size_t)(t0 + i) * NQKV + 32 + lane];
    }
    float m[4], l[4], a0[4], a1[4];
#pragma unroll
    for (int i = 0; i < 4; i++) { m[i] = -1e30f; l[i] = 0.f; a0[i] = 0.f; a1[i] = 0.f; }

    const float scale = 0.125f;
    const int send = t0 + 3;

    for (int sc = 0; sc < t0c + 32; sc += SCH) {
#pragma unroll
        for (int j = 0; j < 2; j++) {
            int flat4 = tid * 2 + j;
            int srow = flat4 >> 4, c4 = (flat4 & 15) * 4;
            size_t goff = (size_t)(sc + srow) * NQKV + c4;
            *reinterpret_cast<float4*>(&Ks[srow * NHS + c4]) =
                *reinterpret_cast<const float4*>(kb + goff);
            *reinterpret_cast<float4*>(&Vs[srow * NHS + c4]) =
                *reinterpret_cast<const float4*>(vb + goff);
        }
        __syncthreads();

        const int L = min(SCH, send - sc + 1);
        for (int s = 0; s < L; s++) {
            float k0v = Ks[s * NHS + lane],      k1v = Ks[s * NHS + 32 + lane];
            float v0v = Vs[s * NHS + lane],      v1v = Vs[s * NHS + 32 + lane];
            const int sg = sc + s;
#pragma unroll
            for (int i = 0; i < 4; i++) {
                float p = q0[i] * k0v + q1[i] * k1v;
                p += __shfl_xor_sync(0xffffffffu, p, 16);
                p += __shfl_xor_sync(0xffffffffu, p, 8);
                p += __shfl_xor_sync(0xffffffffu, p, 4);
                p += __shfl_xor_sync(0xffffffffu, p, 2);
                p += __shfl_xor_sync(0xffffffffu, p, 1);
                if (sg <= t0 + i) {
                    float sc2 = p * scale;
                    float mn = fmaxf(m[i], sc2);
                    float corr = __expf(m[i] - mn);
                    float e = __expf(sc2 - mn);
                    l[i]  = l[i]  * corr + e;
                    a0[i] = a0[i] * corr + e * v0v;
                    a1[i] = a1[i] * corr + e * v1v;
                    m[i] = mn;
                }
            }
        }
        __syncthreads();
    }

#pragma unroll
    for (int i = 0; i < 4; i++) {
        size_t oo = (size_t)(b * NT + t0 + i) * ND + h * NHS + lane;
        o[oo]      = __float2half(a0[i] / l[i]);
        o[oo + 32] = __float2half(a1[i] / l[i]);
    }
}

// ---------------- loss ------------------------------------------------------
__global__ __launch_bounds__(256)
void loss_kernel(const float* __restrict__ logits, const int* __restrict__ targets) {
    __shared__ float sm_[256], sl_[256];
    int row = blockIdx.x, tid = threadIdx.x;
    const float* lr = logits + (size_t)row * NV;
    float m = -1e30f, l = 0.0f;
    for (int j = tid; j < NV; j += 256) {
        float v = lr[j];
        float mn = fmaxf(m, v);
        l = l * __expf(m - mn) + __expf(v - mn);
        m = mn;
    }
    sm_[tid] = m; sl_[tid] = l;
    __syncthreads();
    for (int off = 128; off; off >>= 1) {
        if (tid < off) {
            float m2 = sm_[tid + off], l2 = sl_[tid + off];
            float mn = fmaxf(sm_[tid], m2);
            sl_[tid] = sl_[tid] * __expf(sm_[tid] - mn) + l2 * __expf(m2 - mn);
            sm_[tid] = mn;
        }
        __syncthreads();
    }
    if (tid == 0) {
        float lp = lr[targets[row]] - sm_[0] - logf(sl_[0]);
        atomicAdd(&g_loss, -lp * (1.0f / NTOK));
    }
}

__global__ void finalize_loss_kernel(float* out, int out_size) {
    long long pos = (long long)NTOK * NV;
    if ((long long)out_size > pos) out[pos] = g_loss;
}

// ---------------- host orchestration ----------------------------------------
extern "C" void kernel_launch(void* const* d_in, const int* in_sizes, int n_in,
                              void* d_out, int out_size) {
    const int*   idx     = (const int*)d_in[0];
    const int*   targets = (const int*)d_in[1];
    const float* tok_emb = (const float*)d_in[2];
    const float* pos_emb = (const float*)d_in[3];
    const float* wq      = (const float*)d_in[4];
    const float* wk      = (const float*)d_in[5];
    const float* wv      = (const float*)d_in[6];
    const float* wo      = (const float*)d_in[7];
    const float* bo      = (const float*)d_in[8];
    const float* ln1_s   = (const float*)d_in[9];
    const float* ln1_b   = (const float*)d_in[10];
    const float* ln2_s   = (const float*)d_in[11];
    const float* ln2_b   = (const float*)d_in[12];
    const float* w1      = (const float*)d_in[13];
    const float* b1      = (const float*)d_in[14];
    const float* w2      = (const float*)d_in[15];
    const float* b2      = (const float*)d_in[16];
    const float* lnf_s   = (const float*)d_in[17];
    const float* lnf_b   = (const float*)d_in[18];
    const float* head_w  = (const float*)d_in[19];
    const float* head_b  = (const float*)d_in[20];
    float* out = (float*)d_out;
    (void)in_sizes; (void)n_in;

    float  *px, *pqkv;
    __half *ph, *po, *pmlp, *pwqkvT, *pwoT, *pw1T, *pw2T, *pheadT;
    cudaGetSymbolAddress((void**)&px,     g_x);
    cudaGetSymbolAddress((void**)&ph,     g_h);
    cudaGetSymbolAddress((void**)&pqkv,   g_qkv);
    cudaGetSymbolAddress((void**)&po,     g_o);
    cudaGetSymbolAddress((void**)&pmlp,   g_mlp);
    cudaGetSymbolAddress((void**)&pwqkvT, g_wqkvT);
    cudaGetSymbolAddress((void**)&pwoT,   g_woT);
    cudaGetSymbolAddress((void**)&pw1T,   g_w1T);
    cudaGetSymbolAddress((void**)&pw2T,   g_w2T);
    cudaGetSymbolAddress((void**)&pheadT, g_headT);

    reset_loss_kernel<<<1, 1>>>();
    {
        int total = NL * NQKV * ND;
        repack_qkv_kernel<<<(total + 255) / 256, 256>>>(wq, wk, wv);
    }
    {
        dim3 blk(32, 8);
        transpose_kernel<<<dim3(24, 24, NL), blk>>>(wo, pwoT, ND, ND);
        transpose_kernel<<<dim3(96, 24, NL), blk>>>(w1, pw1T, ND, NFF);
        transpose_kernel<<<dim3(24, 96, NL), blk>>>(w2, pw2T, NFF, ND);
        transpose_kernel<<<dim3((NV + 31) / 32, 24, 1), blk>>>(head_w, pheadT, ND, NV);
    }
    {
        int total = NTOK * ND;
        embed_kernel<<<(total + 255) / 256, 256>>>(idx, tok_emb, pos_emb);
    }

    dim3 gQKV(NTOK / 128, NQKV / 128);
    dim3 gD64(NTOK / 64, ND / 128);      // 64x6 = 384 CTAs (full fill)
    dim3 gFF(NTOK / 128, NFF / 128);
    dim3 gV(NTOK / 128, (NV + 127) / 128);

    const int attnGrid = NB * NH * (NT / 32);

    for (int l = 0; l < NL; l++) {
        ln_kernel<<<NTOK, 256>>>(px, ln1_s + l * ND, ln1_b + l * ND, ph);
        hgemm<0, float><<<gQKV, 256>>>(ph, pwqkvT + (size_t)l * NQKV * ND,
                                       nullptr, nullptr, pqkv, NTOK, NQKV, ND);
        attn_kernel<<<attnGrid, 256>>>(pqkv, po);
        hgemm64<5, float><<<gD64, 256>>>(po, pwoT + (size_t)l * ND * ND,
                                         bo + l * ND, px, px, NTOK, ND, ND);
        ln_kernel<<<NTOK, 256>>>(px, ln2_s + l * ND, ln2_b + l * ND, ph);
        hgemm<3, __half><<<gFF, 256>>>(ph, pw1T + (size_t)l * ND * NFF,
                                       b1 + l * NFF, nullptr, pmlp, NTOK, NFF, ND);
        hgemm64<5, float><<<gD64, 256>>>(pmlp, pw2T + (size_t)l * NFF * ND,
                                         b2 + l * ND, px, px, NTOK, ND, NFF);
    }

    ln_kernel<<<NTOK, 256>>>(px, lnf_s, lnf_b, ph);
    hgemm<1, float><<<gV, 256>>>(ph, pheadT, head_b, nullptr, out, NTOK, NV, ND);
    loss_kernel<<<NTOK, 256>>>(out, targets);
    finalize_loss_kernel<<<1, 1>>>(out, out_size);
}

// round 16
// speedup vs baseline: 1.0640x; 1.0640x over previous
#include <cuda_runtime.h>
#include <cuda_fp16.h>
#include <math.h>
#include <stdint.h>

// Model dims
#define NB   2
#define NT   2048
#define ND   768
#define NH   12
#define NHS  64
#define NL   6
#define NV   50257
#define NTOK (NB*NT)        // 4096
#define NQKV (3*ND)         // 2304
#define NFF  (4*ND)         // 3072

// ---------------- scratch (static device memory; no allocations) -----------
__device__ float  g_x[NTOK*ND];
__device__ __half g_h[NTOK*ND];
__device__ float  g_qkv[(size_t)NTOK*NQKV];
__device__ __half g_o[NTOK*ND];
__device__ __half g_mlp[(size_t)NTOK*NFF];
__device__ __half g_wqkvT[(size_t)NL*NQKV*ND];     // [l][n][k] fp16
__device__ __half g_woT [(size_t)NL*ND*ND];        // [l][n][k] fp16
__device__ __half g_w1T [(size_t)NL*NFF*ND];       // [l][n][k] fp16
__device__ __half g_w2T [(size_t)NL*ND*NFF];       // [l][n][k] fp16
__device__ __half g_headT[(size_t)NV*ND];          // [n][k]    fp16
__device__ float  g_loss;

// ---------------- small utility kernels ------------------------------------
__global__ void reset_loss_kernel() { g_loss = 0.0f; }

__global__ void repack_qkv_kernel(const float* __restrict__ wq,
                                  const float* __restrict__ wk,
                                  const float* __restrict__ wv) {
    int i = blockIdx.x * 256 + threadIdx.x;
    const int total = NL * NQKV * ND;
    if (i >= total) return;
    int d = i % ND;
    int c = (i / ND) % NQKV;
    int l = i / (ND * NQKV);
    int sec = c / ND;
    int c2  = c % ND;
    int h   = c2 / NHS;
    int e   = c2 % NHS;
    const float* w = (sec == 0) ? wq : (sec == 1) ? wk : wv;
    g_wqkvT[i] = __float2half(w[(((size_t)l * NH + h) * ND + d) * NHS + e]);
}

__global__ void transpose_kernel(const float* __restrict__ src,
                                 __half* __restrict__ dst, int R, int C) {
    __shared__ float t[32][33];
    size_t boff = (size_t)blockIdx.z * R * C;
    int c0 = blockIdx.x * 32, r0 = blockIdx.y * 32;
#pragma unroll
    for (int i = 0; i < 32; i += 8) {
        int x = c0 + threadIdx.x, y = r0 + threadIdx.y + i;
        if (x < C && y < R) t[threadIdx.y + i][threadIdx.x] = src[boff + (size_t)y * C + x];
    }
    __syncthreads();
#pragma unroll
    for (int i = 0; i < 32; i += 8) {
        int x = r0 + threadIdx.x, y = c0 + threadIdx.y + i;
        if (x < R && y < C)
            dst[boff + (size_t)y * R + x] = __float2half(t[threadIdx.x][threadIdx.y + i]);
    }
}

__global__ void embed_kernel(const int* __restrict__ idx,
                             const float* __restrict__ tok,
                             const float* __restrict__ pos) {
    int i = blockIdx.x * 256 + threadIdx.x;
    if (i >= NTOK * ND) return;
    int d = i % ND;
    int row = i / ND;
    int t = row % NT;
    int tokid = idx[row];
    g_x[i] = tok[(size_t)tokid * ND + d] + pos[t * ND + d];
}

// x[row][d] += bias[d]   (pre-stage bias for split-K atomic GEMMs)
__global__ void bias_add_kernel(float* __restrict__ x, const float* __restrict__ bias) {
    int i = blockIdx.x * 256 + threadIdx.x;
    if (i < NTOK * ND) x[i] += bias[i % ND];
}

// ---------------- layernorm (fp32 in, fp16 out) -----------------------------
__global__ __launch_bounds__(256)
void ln_kernel(const float* __restrict__ x, const float* __restrict__ s,
               const float* __restrict__ b, __half* __restrict__ out) {
    __shared__ float red[256];
    int row = blockIdx.x, tid = threadIdx.x;
    const float* xr = x + (size_t)row * ND;
    float v0 = xr[tid], v1 = xr[tid + 256], v2 = xr[tid + 512];
    red[tid] = v0 + v1 + v2;
    __syncthreads();
    for (int off = 128; off; off >>= 1) {
        if (tid < off) red[tid] += red[tid + off];
        __syncthreads();
    }
    float mean = red[0] * (1.0f / ND);
    __syncthreads();
    float d0 = v0 - mean, d1 = v1 - mean, d2 = v2 - mean;
    red[tid] = d0 * d0 + d1 * d1 + d2 * d2;
    __syncthreads();
    for (int off = 128; off; off >>= 1) {
        if (tid < off) red[tid] += red[tid + off];
        __syncthreads();
    }
    float rstd = rsqrtf(red[0] * (1.0f / ND) + 1e-5f);
    __half* orow = out + (size_t)row * ND;
    orow[tid]       = __float2half(d0 * rstd * s[tid]       + b[tid]);
    orow[tid + 256] = __float2half(d1 * rstd * s[tid + 256] + b[tid + 256]);
    orow[tid + 512] = __float2half(d2 * rstd * s[tid + 512] + b[tid + 512]);
}

// ---------------- FP16 tensor-core GEMM (R11 proven) ------------------------
// C[MxN] = A[MxK] @ Bt[NxK]^T  (+bias, +relu, +resid); A, Bt fp16 at rest.
// Block 128x128, BK=16, 256 threads = 8 warps (2x4), warp tile 64x32.

#define HSTR 24   // halves per smem row

__device__ __forceinline__ void store_out(float* p, float v)  { *p = v; }
__device__ __forceinline__ void store_out(__half* p, float v) { *p = __float2half(v); }

template <int EPI, typename CT>  // bit0: +bias[n], bit1: relu, bit2: +resid[m,n]
__global__ __launch_bounds__(256)
void hgemm(const __half* __restrict__ A, const __half* __restrict__ Bt,
           const float* __restrict__ bias, const float* __restrict__ resid,
           CT* __restrict__ C, int M, int N, int K) {
    __shared__ __align__(16) __half As[128 * HSTR];
    __shared__ __align__(16) __half Bs[128 * HSTR];
    const int tid  = threadIdx.x;
    const int lane = tid & 31;
    const int warp = tid >> 5;
    const int wm = (warp >> 2) * 64;
    const int wn = (warp & 3) * 32;
    const int row0 = blockIdx.x * 128, col0 = blockIdx.y * 128;

    float acc[4][4][4];
#pragma unroll
    for (int mf = 0; mf < 4; mf++)
#pragma unroll
        for (int nf = 0; nf < 4; nf++)
#pragma unroll
            for (int j = 0; j < 4; j++) acc[mf][nf][j] = 0.0f;

    const int r  = tid >> 1;
    const int hc = (tid & 1) * 8;
    const __half* Ap = A + (size_t)(row0 + r) * K + hc;
    const int  rb  = col0 + r;
    const bool bok = rb < N;
    const __half* Bp = Bt + (size_t)(bok ? rb : 0) * K + hc;

    uint4 pa, pb;
    const uint4 zero4 = make_uint4(0u, 0u, 0u, 0u);
    const int KT = K / 16;

    pa = *reinterpret_cast<const uint4*>(Ap);
    pb = bok ? *reinterpret_cast<const uint4*>(Bp) : zero4;

    for (int kt = 0; kt < KT; kt++) {
        *reinterpret_cast<uint4*>(&As[r * HSTR + hc]) = pa;
        *reinterpret_cast<uint4*>(&Bs[r * HSTR + hc]) = pb;
        __syncthreads();
        if (kt + 1 < KT) {
            int k0 = (kt + 1) * 16;
            pa = *reinterpret_cast<const uint4*>(Ap + k0);
            pb = bok ? *reinterpret_cast<const uint4*>(Bp + k0) : zero4;
        }

        const int g   = lane >> 2;
        const int kq2 = (lane & 3) * 2;
        unsigned af[4][4], bf[4][2];
#pragma unroll
        for (int mf = 0; mf < 4; mf++) {
            int m = wm + mf * 16 + g;
            af[mf][0] = *reinterpret_cast<const unsigned*>(&As[m * HSTR + kq2]);
            af[mf][1] = *reinterpret_cast<const unsigned*>(&As[(m + 8) * HSTR + kq2]);
            af[mf][2] = *reinterpret_cast<const unsigned*>(&As[m * HSTR + kq2 + 8]);
            af[mf][3] = *reinterpret_cast<const unsigned*>(&As[(m + 8) * HSTR + kq2 + 8]);
        }
#pragma unroll
        for (int nf = 0; nf < 4; nf++) {
            int n = wn + nf * 8 + g;
            bf[nf][0] = *reinterpret_cast<const unsigned*>(&Bs[n * HSTR + kq2]);
            bf[nf][1] = *reinterpret_cast<const unsigned*>(&Bs[n * HSTR + kq2 + 8]);
        }
#pragma unroll
        for (int mf = 0; mf < 4; mf++)
#pragma unroll
            for (int nf = 0; nf < 4; nf++)
                asm volatile(
                    "mma.sync.aligned.m16n8k16.row.col.f32.f16.f16.f32 "
                    "{%0,%1,%2,%3}, {%4,%5,%6,%7}, {%8,%9}, {%0,%1,%2,%3};"
                    : "+f"(acc[mf][nf][0]), "+f"(acc[mf][nf][1]),
                      "+f"(acc[mf][nf][2]), "+f"(acc[mf][nf][3])
                    : "r"(af[mf][0]), "r"(af[mf][1]), "r"(af[mf][2]), "r"(af[mf][3]),
                      "r"(bf[nf][0]), "r"(bf[nf][1]));
        __syncthreads();
    }

#pragma unroll
    for (int mf = 0; mf < 4; mf++) {
        int r0 = row0 + wm + mf * 16 + (lane >> 2);
#pragma unroll
        for (int nf = 0; nf < 4; nf++) {
            int n0 = col0 + wn + nf * 8 + 2 * (lane & 3);
#pragma unroll
            for (int half = 0; half < 2; half++) {
                int rr = r0 + half * 8;
#pragma unroll
                for (int j = 0; j < 2; j++) {
                    int n = n0 + j;
                    if (n < N) {
                        float v = acc[mf][nf][half * 2 + j];
                        if (EPI & 1) v += bias[n];
                        if (EPI & 2) v = fmaxf(v, 0.0f);
                        if (EPI & 4) v += resid[(size_t)rr * N + n];
                        store_out(&C[(size_t)rr * N + n], v);
                    }
                }
            }
        }
    }
}

// ---------------- split-K variant: C += A@Bt^T slice via atomicAdd ----------
// Same 128x128 tile / inner loop as hgemm. blockIdx.z selects the K slice
// (Ksub = Kstride / gridDim.z). C must be pre-initialized (resid + bias).
__global__ __launch_bounds__(256)
void hgemm_sk(const __half* __restrict__ A, const __half* __restrict__ Bt,
              float* __restrict__ C, int M, int N, int Kstride, int Ksub) {
    __shared__ __align__(16) __half As[128 * HSTR];
    __shared__ __align__(16) __half Bs[128 * HSTR];
    const int tid  = threadIdx.x;
    const int lane = tid & 31;
    const int warp = tid >> 5;
    const int wm = (warp >> 2) * 64;
    const int wn = (warp & 3) * 32;
    const int row0 = blockIdx.x * 128, col0 = blockIdx.y * 128;
    const int kOff = blockIdx.z * Ksub;

    float acc[4][4][4];
#pragma unroll
    for (int mf = 0; mf < 4; mf++)
#pragma unroll
        for (int nf = 0; nf < 4; nf++)
#pragma unroll
            for (int j = 0; j < 4; j++) acc[mf][nf][j] = 0.0f;

    const int r  = tid >> 1;
    const int hc = (tid & 1) * 8;
    const __half* Ap = A + (size_t)(row0 + r) * Kstride + kOff + hc;
    const __half* Bp = Bt + (size_t)(col0 + r) * Kstride + kOff + hc;

    uint4 pa, pb;
    const int KT = Ksub / 16;

    pa = *reinterpret_cast<const uint4*>(Ap);
    pb = *reinterpret_cast<const uint4*>(Bp);

    for (int kt = 0; kt < KT; kt++) {
        *reinterpret_cast<uint4*>(&As[r * HSTR + hc]) = pa;
        *reinterpret_cast<uint4*>(&Bs[r * HSTR + hc]) = pb;
        __syncthreads();
        if (kt + 1 < KT) {
            int k0 = (kt + 1) * 16;
            pa = *reinterpret_cast<const uint4*>(Ap + k0);
            pb = *reinterpret_cast<const uint4*>(Bp + k0);
        }

        const int g   = lane >> 2;
        const int kq2 = (lane & 3) * 2;
        unsigned af[4][4], bf[4][2];
#pragma unroll
        for (int mf = 0; mf < 4; mf++) {
            int m = wm + mf * 16 + g;
            af[mf][0] = *reinterpret_cast<const unsigned*>(&As[m * HSTR + kq2]);
            af[mf][1] = *reinterpret_cast<const unsigned*>(&As[(m + 8) * HSTR + kq2]);
            af[mf][2] = *reinterpret_cast<const unsigned*>(&As[m * HSTR + kq2 + 8]);
            af[mf][3] = *reinterpret_cast<const unsigned*>(&As[(m + 8) * HSTR + kq2 + 8]);
        }
#pragma unroll
        for (int nf = 0; nf < 4; nf++) {
            int n = wn + nf * 8 + g;
            bf[nf][0] = *reinterpret_cast<const unsigned*>(&Bs[n * HSTR + kq2]);
            bf[nf][1] = *reinterpret_cast<const unsigned*>(&Bs[n * HSTR + kq2 + 8]);
        }
#pragma unroll
        for (int mf = 0; mf < 4; mf++)
#pragma unroll
            for (int nf = 0; nf < 4; nf++)
                asm volatile(
                    "mma.sync.aligned.m16n8k16.row.col.f32.f16.f16.f32 "
                    "{%0,%1,%2,%3}, {%4,%5,%6,%7}, {%8,%9}, {%0,%1,%2,%3};"
                    : "+f"(acc[mf][nf][0]), "+f"(acc[mf][nf][1]),
                      "+f"(acc[mf][nf][2]), "+f"(acc[mf][nf][3])
                    : "r"(af[mf][0]), "r"(af[mf][1]), "r"(af[mf][2]), "r"(af[mf][3]),
                      "r"(bf[nf][0]), "r"(bf[nf][1]));
        __syncthreads();
    }

#pragma unroll
    for (int mf = 0; mf < 4; mf++) {
        int r0 = row0 + wm + mf * 16 + (lane >> 2);
#pragma unroll
        for (int nf = 0; nf < 4; nf++) {
            int n0 = col0 + wn + nf * 8 + 2 * (lane & 3);
#pragma unroll
            for (int half = 0; half < 2; half++) {
                int rr = r0 + half * 8;
#pragma unroll
                for (int j = 0; j < 2; j++) {
                    int n = n0 + j;
                    atomicAdd(&C[(size_t)rr * N + n], acc[mf][nf][half * 2 + j]);
                }
            }
        }
    }
}

// ---------------- smem-tiled streaming causal attention (R11 proven) --------
#define SCH 32    // keys per smem chunk

__global__ __launch_bounds__(256)
void attn_kernel(const float* __restrict__ qkv, __half* __restrict__ o) {
    __shared__ float Ks[SCH * NHS];
    __shared__ float Vs[SCH * NHS];

    const int tid  = threadIdx.x;
    const int lane = tid & 31;
    const int wi   = tid >> 5;
    const int qblk = blockIdx.x % (NT / 32);
    const int bh   = blockIdx.x / (NT / 32);
    const int b    = bh / NH, h = bh % NH;
    const int t0c  = qblk * 32;
    const int t0   = t0c + wi * 4;

    const float* base = qkv + (size_t)b * NT * NQKV;
    const float* qb = base + h * NHS;
    const float* kb = base + ND + h * NHS;
    const float* vb = base + 2 * ND + h * NHS;

    float q0[4], q1[4];
#pragma unroll
    for (int i = 0; i < 4; i++) {
        q0[i] = qb[(size_t)(t0 + i) * NQKV + lane];
        q1[i] = qb[(size_t)(t0 + i) * NQKV + 32 + lane];
    }
    float m[4], l[4], a0[4], a1[4];
#pragma unroll
    for (int i = 0; i < 4; i++) { m[i] = -1e30f; l[i] = 0.f; a0[i] = 0.f; a1[i] = 0.f; }

    const float scale = 0.125f;
    const int send = t0 + 3;

    for (int sc = 0; sc < t0c + 32; sc += SCH) {
#pragma unroll
        for (int j = 0; j < 2; j++) {
            int flat4 = tid * 2 + j;
            int srow = flat4 >> 4, c4 = (flat4 & 15) * 4;
            size_t goff = (size_t)(sc + srow) * NQKV + c4;
            *reinterpret_cast<float4*>(&Ks[srow * NHS + c4]) =
                *reinterpret_cast<const float4*>(kb + goff);
            *reinterpret_cast<float4*>(&Vs[srow * NHS + c4]) =
                *reinterpret_cast<const float4*>(vb + goff);
        }
        __syncthreads();

        const int L = min(SCH, send - sc + 1);
        for (int s = 0; s < L; s++) {
            float k0v = Ks[s * NHS + lane],      k1v = Ks[s * NHS + 32 + lane];
            float v0v = Vs[s * NHS + lane],      v1v = Vs[s * NHS + 32 + lane];
            const int sg = sc + s;
#pragma unroll
            for (int i = 0; i < 4; i++) {
                float p = q0[i] * k0v + q1[i] * k1v;
                p += __shfl_xor_sync(0xffffffffu, p, 16);
                p += __shfl_xor_sync(0xffffffffu, p, 8);
                p += __shfl_xor_sync(0xffffffffu, p, 4);
                p += __shfl_xor_sync(0xffffffffu, p, 2);
                p += __shfl_xor_sync(0xffffffffu, p, 1);
                if (sg <= t0 + i) {
                    float sc2 = p * scale;
                    float mn = fmaxf(m[i], sc2);
                    float corr = __expf(m[i] - mn);
                    float e = __expf(sc2 - mn);
                    l[i]  = l[i]  * corr + e;
                    a0[i] = a0[i] * corr + e * v0v;
                    a1[i] = a1[i] * corr + e * v1v;
                    m[i] = mn;
                }
            }
        }
        __syncthreads();
    }

#pragma unroll
    for (int i = 0; i < 4; i++) {
        size_t oo = (size_t)(b * NT + t0 + i) * ND + h * NHS + lane;
        o[oo]      = __float2half(a0[i] / l[i]);
        o[oo + 32] = __float2half(a1[i] / l[i]);
    }
}

// ---------------- loss ------------------------------------------------------
__global__ __launch_bounds__(256)
void loss_kernel(const float* __restrict__ logits, const int* __restrict__ targets) {
    __shared__ float sm_[256], sl_[256];
    int row = blockIdx.x, tid = threadIdx.x;
    const float* lr = logits + (size_t)row * NV;
    float m = -1e30f, l = 0.0f;
    for (int j = tid; j < NV; j += 256) {
        float v = lr[j];
        float mn = fmaxf(m, v);
        l = l * __expf(m - mn) + __expf(v - mn);
        m = mn;
    }
    sm_[tid] = m; sl_[tid] = l;
    __syncthreads();
    for (int off = 128; off; off >>= 1) {
        if (tid < off) {
            float m2 = sm_[tid + off], l2 = sl_[tid + off];
            float mn = fmaxf(sm_[tid], m2);
            sl_[tid] = sl_[tid] * __expf(sm_[tid] - mn) + l2 * __expf(m2 - mn);
            sm_[tid] = mn;
        }
        __syncthreads();
    }
    if (tid == 0) {
        float lp = lr[targets[row]] - sm_[0] - logf(sl_[0]);
        atomicAdd(&g_loss, -lp * (1.0f / NTOK));
    }
}

__global__ void finalize_loss_kernel(float* out, int out_size) {
    long long pos = (long long)NTOK * NV;
    if ((long long)out_size > pos) out[pos] = g_loss;
}

// ---------------- host orchestration ----------------------------------------
extern "C" void kernel_launch(void* const* d_in, const int* in_sizes, int n_in,
                              void* d_out, int out_size) {
    const int*   idx     = (const int*)d_in[0];
    const int*   targets = (const int*)d_in[1];
    const float* tok_emb = (const float*)d_in[2];
    const float* pos_emb = (const float*)d_in[3];
    const float* wq      = (const float*)d_in[4];
    const float* wk      = (const float*)d_in[5];
    const float* wv      = (const float*)d_in[6];
    const float* wo      = (const float*)d_in[7];
    const float* bo      = (const float*)d_in[8];
    const float* ln1_s   = (const float*)d_in[9];
    const float* ln1_b   = (const float*)d_in[10];
    const float* ln2_s   = (const float*)d_in[11];
    const float* ln2_b   = (const float*)d_in[12];
    const float* w1      = (const float*)d_in[13];
    const float* b1      = (const float*)d_in[14];
    const float* w2      = (const float*)d_in[15];
    const float* b2      = (const float*)d_in[16];
    const float* lnf_s   = (const float*)d_in[17];
    const float* lnf_b   = (const float*)d_in[18];
    const float* head_w  = (const float*)d_in[19];
    const float* head_b  = (const float*)d_in[20];
    float* out = (float*)d_out;
    (void)in_sizes; (void)n_in;

    float  *px, *pqkv;
    __half *ph, *po, *pmlp, *pwqkvT, *pwoT, *pw1T, *pw2T, *pheadT;
    cudaGetSymbolAddress((void**)&px,     g_x);
    cudaGetSymbolAddress((void**)&ph,     g_h);
    cudaGetSymbolAddress((void**)&pqkv,   g_qkv);
    cudaGetSymbolAddress((void**)&po,     g_o);
    cudaGetSymbolAddress((void**)&pmlp,   g_mlp);
    cudaGetSymbolAddress((void**)&pwqkvT, g_wqkvT);
    cudaGetSymbolAddress((void**)&pwoT,   g_woT);
    cudaGetSymbolAddress((void**)&pw1T,   g_w1T);
    cudaGetSymbolAddress((void**)&pw2T,   g_w2T);
    cudaGetSymbolAddress((void**)&pheadT, g_headT);

    reset_loss_kernel<<<1, 1>>>();
    {
        int total = NL * NQKV * ND;
        repack_qkv_kernel<<<(total + 255) / 256, 256>>>(wq, wk, wv);
    }
    {
        dim3 blk(32, 8);
        transpose_kernel<<<dim3(24, 24, NL), blk>>>(wo, pwoT, ND, ND);
        transpose_kernel<<<dim3(96, 24, NL), blk>>>(w1, pw1T, ND, NFF);
        transpose_kernel<<<dim3(24, 96, NL), blk>>>(w2, pw2T, NFF, ND);
        transpose_kernel<<<dim3((NV + 31) / 32, 24, 1), blk>>>(head_w, pheadT, ND, NV);
    }
    {
        int total = NTOK * ND;
        embed_kernel<<<(total + 255) / 256, 256>>>(idx, tok_emb, pos_emb);
    }

    dim3 gQKV(NTOK / 128, NQKV / 128);
    dim3 gSK(NTOK / 128, ND / 128, 3);   // split-K x3: 576 CTAs (~97% fill)
    dim3 gFF(NTOK / 128, NFF / 128);
    dim3 gV(NTOK / 128, (NV + 127) / 128);
    const int nBias = (NTOK * ND + 255) / 256;

    const int attnGrid = NB * NH * (NT / 32);

    for (int l = 0; l < NL; l++) {
        ln_kernel<<<NTOK, 256>>>(px, ln1_s + l * ND, ln1_b + l * ND, ph);
        hgemm<0, float><<<gQKV, 256>>>(ph, pwqkvT + (size_t)l * NQKV * ND,
                                       nullptr, nullptr, pqkv, NTOK, NQKV, ND);
        attn_kernel<<<attnGrid, 256>>>(pqkv, po);
        // x += bo; x += o @ wo  (split-K x3, atomic accumulate)
        bias_add_kernel<<<nBias, 256>>>(px, bo + l * ND);
        hgemm_sk<<<gSK, 256>>>(po, pwoT + (size_t)l * ND * ND,
                               px, NTOK, ND, ND, ND / 3);
        ln_kernel<<<NTOK, 256>>>(px, ln2_s + l * ND, ln2_b + l * ND, ph);
        hgemm<3, __half><<<gFF, 256>>>(ph, pw1T + (size_t)l * ND * NFF,
                                       b1 + l * NFF, nullptr, pmlp, NTOK, NFF, ND);
        // x += b2; x += relu_mlp @ w2  (split-K x3)
        bias_add_kernel<<<nBias, 256>>>(px, b2 + l * ND);
        hgemm_sk<<<gSK, 256>>>(pmlp, pw2T + (size_t)l * NFF * ND,
                               px, NTOK, ND, NFF, NFF / 3);
    }

    ln_kernel<<<NTOK, 256>>>(px, lnf_s, lnf_b, ph);
    hgemm<1, float><<<gV, 256>>>(ph, pheadT, head_b, nullptr, out, NTOK, NV, ND);
    loss_kernel<<<NTOK, 256>>>(out, targets);
    finalize_loss_kernel<<<1, 1>>>(out, out_size);
}